// round 9
// baseline (speedup 1.0000x reference)
#include <cuda_runtime.h>
#include <cuda_fp16.h>
#include <cstdint>

// Problem constants
#define T_  512
#define B_  64
#define NI_ 512
#define NH_ 1024
#define NG_ 4096          // 4*NH
#define TB_ (T_*B_)       // 32768
#define NCTA 128

// ---------------------------------------------------------------------------
// Device scratch (static — no allocations anywhere)
// ---------------------------------------------------------------------------
__device__ __align__(16) __half g_x16[TB_ * NI_];              //  32 MB fp16 input
__device__ __align__(16) __half g_wih[2][NG_ * NI_];           // permuted W_ih [p][k]
__device__ __align__(16) __half g_whh[2][NG_ * NH_];           // permuted W_hh [p][k]
__device__ __align__(16) float  g_bias[2][NG_];                // b_ih+b_hh, permuted
__device__ __align__(16) __half g_xw[2][(size_t)TB_ * NG_];    // 536 MB x@W_ih^T + biases
__device__ __align__(16) __half g_h16[2][B_ * NH_];            // h ping-pong (fp16)
__device__ __align__(16) float  g_c[B_ * NH_];                 // c state (fp32)
__device__ unsigned g_bar_count;
__device__ unsigned g_bar_gen;

// ---------------------------------------------------------------------------
// PTX helpers
// ---------------------------------------------------------------------------
__device__ __forceinline__ void cp16(void* dst, const void* src) {
    uint32_t d = (uint32_t)__cvta_generic_to_shared(dst);
    asm volatile("cp.async.cg.shared.global [%0], [%1], 16;\n" :: "r"(d), "l"(src));
}
__device__ __forceinline__ void cp_commit() {
    asm volatile("cp.async.commit_group;\n");
}
__device__ __forceinline__ void ldsm4(uint32_t* r, const void* p) {
    uint32_t a = (uint32_t)__cvta_generic_to_shared(p);
    asm volatile("ldmatrix.sync.aligned.m8n8.x4.shared.b16 {%0,%1,%2,%3}, [%4];\n"
                 : "=r"(r[0]), "=r"(r[1]), "=r"(r[2]), "=r"(r[3]) : "r"(a));
}
__device__ __forceinline__ void mma16816(float* c, const uint32_t* a, uint32_t b0, uint32_t b1) {
    asm volatile(
        "mma.sync.aligned.m16n8k16.row.col.f32.f16.f16.f32 "
        "{%0,%1,%2,%3},{%4,%5,%6,%7},{%8,%9},{%0,%1,%2,%3};\n"
        : "+f"(c[0]), "+f"(c[1]), "+f"(c[2]), "+f"(c[3])
        : "r"(a[0]), "r"(a[1]), "r"(a[2]), "r"(a[3]), "r"(b0), "r"(b1));
}
__device__ __forceinline__ float sigmoidf_(float x) {
    return 1.f / (1.f + __expf(-x));
}

// ---------------------------------------------------------------------------
// Prep kernels
// ---------------------------------------------------------------------------
__global__ void k_convert_x(const float* __restrict__ x) {
    int i = (blockIdx.x * blockDim.x + threadIdx.x) * 4;
    float4 v = *reinterpret_cast<const float4*>(x + i);
    *reinterpret_cast<__half2*>(g_x16 + i)     = __floats2half2_rn(v.x, v.y);
    *reinterpret_cast<__half2*>(g_x16 + i + 2) = __floats2half2_rn(v.z, v.w);
}

// Permutation: p = 4*j + g  <->  original row r = g*NH + j   (gate order i,f,g,o)
__global__ void k_prep(const float* __restrict__ wih_e, const float* __restrict__ whh_e,
                       const float* __restrict__ bih_e, const float* __restrict__ bhh_e,
                       const float* __restrict__ wih_d, const float* __restrict__ whh_d,
                       const float* __restrict__ bih_d, const float* __restrict__ bhh_d) {
    const long total = 2L * NG_ * NH_;
    for (long i = (long)blockIdx.x * blockDim.x + threadIdx.x; i < total;
         i += (long)gridDim.x * blockDim.x) {
        int  e   = (i >= (long)NG_ * NH_);
        long rem = i - (long)e * NG_ * NH_;
        int  p   = (int)(rem >> 10);
        int  k   = (int)(rem & (NH_ - 1));
        int  r   = ((p & 3) << 10) + (p >> 2);        // g*1024 + j
        const float* whh = e ? whh_d : whh_e;
        g_whh[e][p * NH_ + k] = __float2half(whh[r * NH_ + k]);
        if (k < NI_) {
            const float* wih = e ? wih_d : wih_e;
            g_wih[e][p * NI_ + k] = __float2half(wih[r * NI_ + k]);
        }
        if (k == 0) {
            g_bias[e][p] = e ? (bih_d[r] + bhh_d[r]) : (bih_e[r] + bhh_e[r]);
        }
    }
}

__global__ void k_init() {
    int i = blockIdx.x * blockDim.x + threadIdx.x;
    if (i < B_ * NH_) {
        g_h16[0][i] = __float2half(0.f);
        g_c[i] = 0.f;
    }
    if (i == 0) {
        g_bar_count = 0u;
        g_bar_gen   = 0u;
    }
}

// ---------------------------------------------------------------------------
// Input projection GEMM: g_xw[e][tb][p] = x16[tb]·Wih[p] + bias[p]   (fp16 out)
// Tiles: M64 x N64, K=512 (BK=64, 8 iters), 4 warps each 16 rows x 64 cols.
// ---------------------------------------------------------------------------
__global__ void __launch_bounds__(128) k_xw_gemm(int e) {
    const __half* __restrict__ Bw   = g_wih[e];
    const float*  __restrict__ bias = g_bias[e];
    __half*       __restrict__ outp = g_xw[e];

    __shared__ __align__(16) __half sA[2][64][72];
    __shared__ __align__(16) __half sB[2][64][72];

    int tid = threadIdx.x, warp = tid >> 5, lane = tid & 31;
    int mb = blockIdx.y * 64, nb = blockIdx.x * 64;

    float acc[8][4];
#pragma unroll
    for (int i = 0; i < 8; i++)
#pragma unroll
        for (int j = 0; j < 4; j++) acc[i][j] = 0.f;

#pragma unroll
    for (int c = tid; c < 512; c += 128) {
        int r = c >> 3, o = (c & 7) * 8;
        cp16(&sA[0][r][o], g_x16 + (mb + r) * NI_ + o);
    }
#pragma unroll
    for (int c = tid; c < 512; c += 128) {
        int r = c >> 3, o = (c & 7) * 8;
        cp16(&sB[0][r][o], Bw + (nb + r) * NI_ + o);
    }
    cp_commit();

    for (int kt = 0; kt < 8; kt++) {
        if (kt + 1 < 8) {
            int st = (kt + 1) & 1, k0 = (kt + 1) * 64;
#pragma unroll
            for (int c = tid; c < 512; c += 128) {
                int r = c >> 3, o = (c & 7) * 8;
                cp16(&sA[st][r][o], g_x16 + (mb + r) * NI_ + k0 + o);
            }
#pragma unroll
            for (int c = tid; c < 512; c += 128) {
                int r = c >> 3, o = (c & 7) * 8;
                cp16(&sB[st][r][o], Bw + (nb + r) * NI_ + k0 + o);
            }
            cp_commit();
            asm volatile("cp.async.wait_group 1;\n");
        } else {
            asm volatile("cp.async.wait_group 0;\n");
        }
        __syncthreads();
        int st = kt & 1;
#pragma unroll
        for (int ks = 0; ks < 4; ks++) {
            uint32_t a[4];
            ldsm4(a, &sA[st][warp * 16 + (lane & 15)][ks * 16 + ((lane >> 4) << 3)]);
#pragma unroll
            for (int n2 = 0; n2 < 4; n2++) {
                uint32_t b[4];
                int nr = n2 * 16 + (lane & 7) + ((lane >> 4) << 3);
                int kc = ks * 16 + ((lane >> 3) & 1) * 8;
                ldsm4(b, &sB[st][nr][kc]);
                mma16816(acc[n2 * 2 + 0], a, b[0], b[1]);
                mma16816(acc[n2 * 2 + 1], a, b[2], b[3]);
            }
        }
        __syncthreads();
    }

    int r0 = mb + warp * 16 + (lane >> 2);
#pragma unroll
    for (int nt = 0; nt < 8; nt++) {
        int cg = nb + nt * 8 + ((lane & 3) << 1);
        float b0 = bias[cg], b1 = bias[cg + 1];
        __half2 v0 = __floats2half2_rn(acc[nt][0] + b0, acc[nt][1] + b1);
        __half2 v1 = __floats2half2_rn(acc[nt][2] + b0, acc[nt][3] + b1);
        *reinterpret_cast<__half2*>(outp + (size_t)r0 * NG_ + cg)       = v0;
        *reinterpret_cast<__half2*>(outp + (size_t)(r0 + 8) * NG_ + cg) = v1;
    }
}

// ---------------------------------------------------------------------------
// Persistent step kernel. 128 CTAs (one per SM, wave-1 resident). CTA bx owns
// permuted gate cols [32bx,32bx+32) = hidden units [8bx,8bx+8). Per step:
// gates[64x32] = h[64x1024] · Wslice^T, W resident in SMEM for all 1024 steps.
// Steps separated by an L2 atomic generation barrier.
// SMEM: wts 2x32x1032 halves (132096 B) | sA 3x64x72 (27648 B) |
//       sxw 64x32 (4096 B) | gsm 4x16x33 f32 (8448 B)  = 172288 B
// ---------------------------------------------------------------------------
#define SMEM_PERSIST 172288

__global__ void __launch_bounds__(128, 1) k_persist(const float* __restrict__ mask,
                                                    float* __restrict__ outp) {
    extern __shared__ __align__(16) unsigned char smem_raw[];
    __half* wsm = reinterpret_cast<__half*>(smem_raw);        // [2][32][1032]
    __half* sAb = wsm + 2 * 32 * 1032;                        // [3][64][72]
    __half* sxw = sAb + 3 * 64 * 72;                          // [64][32]
    float*  gsm = reinterpret_cast<float*>(sxw + 64 * 32);    // [4][16][33]

    const int tid  = threadIdx.x, warp = tid >> 5, lane = tid & 31;
    const int cta  = blockIdx.x;
    const int c0   = cta * 32;

    // ---- load this CTA's enc+dec weight slices into SMEM (once) ----
    for (int e = 0; e < 2; e++) {
        const __half* src = g_whh[e] + (size_t)c0 * NH_;
        __half* dst = wsm + e * (32 * 1032);
        for (int i = tid; i < 32 * 128; i += 128) {           // 16B chunks
            int r = i >> 7, ch = i & 127;
            cp16(dst + r * 1032 + ch * 8, src + r * NH_ + ch * 8);
        }
    }
    cp_commit();
    asm volatile("cp.async.wait_group 0;\n");
    __syncthreads();

    for (int s = 0; s < 1024; s++) {
        const bool enc = (s < 512);
        const int  t   = enc ? s : s - 512;
        const int  e   = enc ? 0 : 1;
        const __half* __restrict__ hin  = g_h16[s & 1];
        __half*       __restrict__ hout = g_h16[(s + 1) & 1];
        const __half* wB = wsm + e * (32 * 1032);

        // group 0: xw tile + A stage 0    group 1: A stage 1
        {
            const __half* xwsrc = g_xw[e] + (size_t)(t * 64) * NG_ + c0;
            for (int i = tid; i < 256; i += 128) {
                int b = i >> 2, o = (i & 3) * 8;
                cp16(sxw + b * 32 + o, xwsrc + (size_t)b * NG_ + o);
            }
            for (int i = tid; i < 512; i += 128) {
                int r = i >> 3, o = (i & 7) * 8;
                cp16(sAb + r * 72 + o, hin + r * NH_ + o);
            }
            cp_commit();
            for (int i = tid; i < 512; i += 128) {
                int r = i >> 3, o = (i & 7) * 8;
                cp16(sAb + (64 * 72) + r * 72 + o, hin + r * NH_ + 64 + o);
            }
            cp_commit();
        }

        float acc[4][4];
#pragma unroll
        for (int i = 0; i < 4; i++)
#pragma unroll
            for (int j = 0; j < 4; j++) acc[i][j] = 0.f;

        for (int kt = 0; kt < 16; kt++) {
            // wait for stage kt's group, then barrier, THEN overwrite-issue:
            // stage (kt+2)%3 was consumed at iter kt-1; everyone is past it.
            if (kt + 1 < 16) {
                asm volatile("cp.async.wait_group 1;\n");
            } else {
                asm volatile("cp.async.wait_group 0;\n");
            }
            __syncthreads();
            if (kt + 2 < 16) {
                int st = (kt + 2) % 3, k0 = (kt + 2) * 64;
                for (int i = tid; i < 512; i += 128) {
                    int r = i >> 3, o = (i & 7) * 8;
                    cp16(sAb + st * (64 * 72) + r * 72 + o, hin + r * NH_ + k0 + o);
                }
                cp_commit();
            }
            const __half* A = sAb + (kt % 3) * (64 * 72);
#pragma unroll
            for (int ks = 0; ks < 4; ks++) {
                uint32_t a[4];
                ldsm4(a, A + (warp * 16 + (lane & 15)) * 72 + ks * 16 + ((lane >> 4) << 3));
#pragma unroll
                for (int n2 = 0; n2 < 2; n2++) {
                    uint32_t b[4];
                    int nr = n2 * 16 + (lane & 7) + ((lane >> 4) << 3);
                    int kc = kt * 64 + ks * 16 + ((lane >> 3) & 1) * 8;
                    ldsm4(b, wB + nr * 1032 + kc);
                    mma16816(acc[n2 * 2 + 0], a, b[0], b[1]);
                    mma16816(acc[n2 * 2 + 1], a, b[2], b[3]);
                }
            }
            __syncthreads();   // all warps done with stage kt before next overwrite
        }

        // stage accumulators so each lane gathers i,f,g,o of one unit
        {
            int r = lane >> 2;
            float* gw = gsm + warp * (16 * 33);
#pragma unroll
            for (int nt = 0; nt < 4; nt++) {
                int c = nt * 8 + ((lane & 3) << 1);
                gw[r * 33 + c]           = acc[nt][0];
                gw[r * 33 + c + 1]       = acc[nt][1];
                gw[(r + 8) * 33 + c]     = acc[nt][2];
                gw[(r + 8) * 33 + c + 1] = acc[nt][3];
            }
        }
        __syncwarp();

        // LSTM elementwise update: lane handles 4 (b, j) cells
        {
            int rloc = lane >> 1;
            int b    = warp * 16 + rloc;
            int jb   = (lane & 1) * 4;
            const __half* xr = sxw + b * 32;
            const float*  gw = gsm + warp * (16 * 33) + rloc * 33;
            float m = enc ? mask[t * 64 + b] : 1.f;

#pragma unroll
            for (int u = 0; u < 4; u++) {
                int jl  = jb + u;
                int col = jl * 4;
                float gi = gw[col + 0] + __half2float(xr[col + 0]);
                float gf = gw[col + 1] + __half2float(xr[col + 1]);
                float gg = gw[col + 2] + __half2float(xr[col + 2]);
                float go = gw[col + 3] + __half2float(xr[col + 3]);

                float ii = sigmoidf_(gi);
                float ff = sigmoidf_(gf);
                float g2 = tanhf(gg);
                float oo = sigmoidf_(go);

                int   j   = (c0 >> 2) + jl;
                int   idx = b * NH_ + j;
                float cp  = g_c[idx];
                float cn  = ff * cp + ii * g2;
                float hn  = oo * tanhf(cn);

                if (enc) {
                    float hp = __half2float(hin[idx]);   // self-written slice
                    hn = hn * m + hp * (1.f - m);
                    cn = cn * m + cp * (1.f - m);
                }
                g_c[idx]  = cn;
                hout[idx] = __float2half(hn);
                if (!enc) outp[(size_t)(t * 64 + b) * NH_ + j] = hn;
            }
        }

        // ---- grid barrier (release h writes, acquire peers') ----
        if (s != 1023) {
            __threadfence();
            __syncthreads();
            if (tid == 0) {
                unsigned a = atomicAdd(&g_bar_count, 1u);
                if (a == NCTA - 1) {
                    g_bar_count = 0u;
                    __threadfence();
                    atomicAdd(&g_bar_gen, 1u);
                } else {
                    unsigned target = (unsigned)(s + 1);
                    while (*((volatile unsigned*)&g_bar_gen) < target) {
                        __nanosleep(32);
                    }
                }
                __threadfence();
            }
            __syncthreads();
        }
    }
}

// ---------------------------------------------------------------------------
// Launch
// ---------------------------------------------------------------------------
extern "C" void kernel_launch(void* const* d_in, const int* in_sizes, int n_in,
                              void* d_out, int out_size) {
    (void)in_sizes; (void)n_in; (void)out_size;
    const float* input = (const float*)d_in[0];
    const float* mask  = (const float*)d_in[1];
    const float* Wih_e = (const float*)d_in[2];
    const float* Whh_e = (const float*)d_in[3];
    const float* bih_e = (const float*)d_in[4];
    const float* bhh_e = (const float*)d_in[5];
    const float* Wih_d = (const float*)d_in[6];
    const float* Whh_d = (const float*)d_in[7];
    const float* bih_d = (const float*)d_in[8];
    const float* bhh_d = (const float*)d_in[9];
    float* out = (float*)d_out;

    cudaFuncSetAttribute(k_persist, cudaFuncAttributeMaxDynamicSharedMemorySize,
                         SMEM_PERSIST);

    // prep: fp16 conversions, gate-interleaved weight permutation, state reset
    k_convert_x<<<(TB_ * NI_) / 4 / 256, 256>>>(input);
    k_prep<<<2048, 256>>>(Wih_e, Whh_e, bih_e, bhh_e, Wih_d, Whh_d, bih_d, bhh_d);
    k_init<<<(B_ * NH_ + 255) / 256, 256>>>();

    // batched input projections (biases folded in)
    dim3 ggrid(NG_ / 64, TB_ / 64);
    k_xw_gemm<<<ggrid, 128>>>(0);
    k_xw_gemm<<<ggrid, 128>>>(1);

    // single persistent kernel: 512 encoder + 512 decoder steps
    k_persist<<<NCTA, 128, SMEM_PERSIST>>>(mask, out);
}

// round 10
// speedup vs baseline: 1.3689x; 1.3689x over previous
#include <cuda_runtime.h>
#include <cuda_fp16.h>
#include <cstdint>

// Problem constants
#define T_  512
#define B_  64
#define NI_ 512
#define NH_ 1024
#define NG_ 4096          // 4*NH
#define TB_ (T_*B_)       // 32768
#define NCTA 128

// ---------------------------------------------------------------------------
// Device scratch (static — no allocations anywhere)
// ---------------------------------------------------------------------------
__device__ __align__(16) __half g_x16[TB_ * NI_];              //  32 MB fp16 input
__device__ __align__(16) __half g_wih[2][NG_ * NI_];           // permuted W_ih [p][k]
__device__ __align__(16) __half g_whh[2][NG_ * NH_];           // permuted W_hh [p][k]
__device__ __align__(16) float  g_bias[2][NG_];                // b_ih+b_hh, permuted
__device__ __align__(16) __half g_xw[2][(size_t)TB_ * NG_];    // 536 MB x@W_ih^T + biases
__device__ __align__(16) __half g_h16[2][B_ * NH_];            // h ping-pong (fp16)
__device__ unsigned g_bar_count;
__device__ unsigned g_bar_gen;

// ---------------------------------------------------------------------------
// PTX helpers
// ---------------------------------------------------------------------------
__device__ __forceinline__ void cp16(void* dst, const void* src) {
    uint32_t d = (uint32_t)__cvta_generic_to_shared(dst);
    asm volatile("cp.async.cg.shared.global [%0], [%1], 16;\n" :: "r"(d), "l"(src));
}
__device__ __forceinline__ void cp_commit() {
    asm volatile("cp.async.commit_group;\n");
}
__device__ __forceinline__ void ldsm4(uint32_t* r, const void* p) {
    uint32_t a = (uint32_t)__cvta_generic_to_shared(p);
    asm volatile("ldmatrix.sync.aligned.m8n8.x4.shared.b16 {%0,%1,%2,%3}, [%4];\n"
                 : "=r"(r[0]), "=r"(r[1]), "=r"(r[2]), "=r"(r[3]) : "r"(a));
}
__device__ __forceinline__ void mma16816(float* c, const uint32_t* a, uint32_t b0, uint32_t b1) {
    asm volatile(
        "mma.sync.aligned.m16n8k16.row.col.f32.f16.f16.f32 "
        "{%0,%1,%2,%3},{%4,%5,%6,%7},{%8,%9},{%0,%1,%2,%3};\n"
        : "+f"(c[0]), "+f"(c[1]), "+f"(c[2]), "+f"(c[3])
        : "r"(a[0]), "r"(a[1]), "r"(a[2]), "r"(a[3]), "r"(b0), "r"(b1));
}
__device__ __forceinline__ float sigmoidf_(float x) {
    return 1.f / (1.f + __expf(-x));
}

// ---------------------------------------------------------------------------
// Prep kernels
// ---------------------------------------------------------------------------
__global__ void k_convert_x(const float* __restrict__ x) {
    int i = (blockIdx.x * blockDim.x + threadIdx.x) * 4;
    float4 v = *reinterpret_cast<const float4*>(x + i);
    *reinterpret_cast<__half2*>(g_x16 + i)     = __floats2half2_rn(v.x, v.y);
    *reinterpret_cast<__half2*>(g_x16 + i + 2) = __floats2half2_rn(v.z, v.w);
}

// Permutation: p = 4*j + g  <->  original row r = g*NH + j   (gate order i,f,g,o)
__global__ void k_prep(const float* __restrict__ wih_e, const float* __restrict__ whh_e,
                       const float* __restrict__ bih_e, const float* __restrict__ bhh_e,
                       const float* __restrict__ wih_d, const float* __restrict__ whh_d,
                       const float* __restrict__ bih_d, const float* __restrict__ bhh_d) {
    const long total = 2L * NG_ * NH_;
    for (long i = (long)blockIdx.x * blockDim.x + threadIdx.x; i < total;
         i += (long)gridDim.x * blockDim.x) {
        int  e   = (i >= (long)NG_ * NH_);
        long rem = i - (long)e * NG_ * NH_;
        int  p   = (int)(rem >> 10);
        int  k   = (int)(rem & (NH_ - 1));
        int  r   = ((p & 3) << 10) + (p >> 2);        // g*1024 + j
        const float* whh = e ? whh_d : whh_e;
        g_whh[e][p * NH_ + k] = __float2half(whh[r * NH_ + k]);
        if (k < NI_) {
            const float* wih = e ? wih_d : wih_e;
            g_wih[e][p * NI_ + k] = __float2half(wih[r * NI_ + k]);
        }
        if (k == 0) {
            g_bias[e][p] = e ? (bih_d[r] + bhh_d[r]) : (bih_e[r] + bhh_e[r]);
        }
    }
}

__global__ void k_init() {
    int i = blockIdx.x * blockDim.x + threadIdx.x;
    if (i < B_ * NH_) {
        g_h16[0][i] = __float2half(0.f);
    }
    if (i == 0) {
        g_bar_count = 0u;
        g_bar_gen   = 0u;
    }
}

// ---------------------------------------------------------------------------
// Input projection GEMM: g_xw[e][tb][p] = x16[tb]·Wih[p] + bias[p]   (fp16 out)
// Tiles: M64 x N64, K=512 (BK=64, 8 iters). blockIdx.z = enc/dec.
// ---------------------------------------------------------------------------
__global__ void __launch_bounds__(128) k_xw_gemm() {
    const int e = blockIdx.z;
    const __half* __restrict__ Bw   = g_wih[e];
    const float*  __restrict__ bias = g_bias[e];
    __half*       __restrict__ outp = g_xw[e];

    __shared__ __align__(16) __half sA[2][64][72];
    __shared__ __align__(16) __half sB[2][64][72];

    int tid = threadIdx.x, warp = tid >> 5, lane = tid & 31;
    int mb = blockIdx.y * 64, nb = blockIdx.x * 64;

    float acc[8][4];
#pragma unroll
    for (int i = 0; i < 8; i++)
#pragma unroll
        for (int j = 0; j < 4; j++) acc[i][j] = 0.f;

#pragma unroll
    for (int c = tid; c < 512; c += 128) {
        int r = c >> 3, o = (c & 7) * 8;
        cp16(&sA[0][r][o], g_x16 + (mb + r) * NI_ + o);
    }
#pragma unroll
    for (int c = tid; c < 512; c += 128) {
        int r = c >> 3, o = (c & 7) * 8;
        cp16(&sB[0][r][o], Bw + (nb + r) * NI_ + o);
    }
    cp_commit();

    for (int kt = 0; kt < 8; kt++) {
        if (kt + 1 < 8) {
            int st = (kt + 1) & 1, k0 = (kt + 1) * 64;
#pragma unroll
            for (int c = tid; c < 512; c += 128) {
                int r = c >> 3, o = (c & 7) * 8;
                cp16(&sA[st][r][o], g_x16 + (mb + r) * NI_ + k0 + o);
            }
#pragma unroll
            for (int c = tid; c < 512; c += 128) {
                int r = c >> 3, o = (c & 7) * 8;
                cp16(&sB[st][r][o], Bw + (nb + r) * NI_ + k0 + o);
            }
            cp_commit();
            asm volatile("cp.async.wait_group 1;\n");
        } else {
            asm volatile("cp.async.wait_group 0;\n");
        }
        __syncthreads();
        int st = kt & 1;
#pragma unroll
        for (int ks = 0; ks < 4; ks++) {
            uint32_t a[4];
            ldsm4(a, &sA[st][warp * 16 + (lane & 15)][ks * 16 + ((lane >> 4) << 3)]);
#pragma unroll
            for (int n2 = 0; n2 < 4; n2++) {
                uint32_t b[4];
                int nr = n2 * 16 + (lane & 7) + ((lane >> 4) << 3);
                int kc = ks * 16 + ((lane >> 3) & 1) * 8;
                ldsm4(b, &sB[st][nr][kc]);
                mma16816(acc[n2 * 2 + 0], a, b[0], b[1]);
                mma16816(acc[n2 * 2 + 1], a, b[2], b[3]);
            }
        }
        __syncthreads();
    }

    int r0 = mb + warp * 16 + (lane >> 2);
#pragma unroll
    for (int nt = 0; nt < 8; nt++) {
        int cg = nb + nt * 8 + ((lane & 3) << 1);
        float b0 = bias[cg], b1 = bias[cg + 1];
        __half2 v0 = __floats2half2_rn(acc[nt][0] + b0, acc[nt][1] + b1);
        __half2 v1 = __floats2half2_rn(acc[nt][2] + b0, acc[nt][3] + b1);
        *reinterpret_cast<__half2*>(outp + (size_t)r0 * NG_ + cg)       = v0;
        *reinterpret_cast<__half2*>(outp + (size_t)(r0 + 8) * NG_ + cg) = v1;
    }
}

// ---------------------------------------------------------------------------
// Persistent step kernel. 128 CTAs, one per SM. CTA bx owns permuted gate
// cols [32bx,32bx+32) = hidden units [8bx,8bx+8).
// Per step: FULL h operand (64x1024 fp16, 132KB) is loaded into SMEM as 8
// independent cp.async groups (no SMEM reuse within a step -> no WAR
// barriers); chunk c computes after wait_group(7-c). Current-phase W_hh slice
// (32x1024, 66KB) stays resident in SMEM; c-state lives in SMEM (CTA-local).
// SMEM layout (halves unless noted), strides padded to 1032 halves:
//   wsm [32][1032]  66048 B
//   sA  [64][1032] 132096 B
//   sxw [64][32]     4096 B
//   gsm [4][16][33] f32 8448 B
//   csm [64][8]     f32 2048 B      total 212736 B
// ---------------------------------------------------------------------------
#define SMEM_PERSIST 212736

__global__ void __launch_bounds__(128, 1) k_persist(const float* __restrict__ mask,
                                                    float* __restrict__ outp) {
    extern __shared__ __align__(16) unsigned char smem_raw[];
    __half* wsm = reinterpret_cast<__half*>(smem_raw);        // [32][1032]
    __half* sA  = wsm + 32 * 1032;                            // [64][1032]
    __half* sxw = sA + 64 * 1032;                             // [64][32]
    float*  gsm = reinterpret_cast<float*>(sxw + 64 * 32);    // [4][16][33]
    float*  csm = gsm + 4 * 16 * 33;                          // [64][8]

    const int tid  = threadIdx.x, warp = tid >> 5, lane = tid & 31;
    const int cta  = blockIdx.x;
    const int c0   = cta * 32;

    // zero c-state (CTA-local, SMEM-resident)
    for (int i = tid; i < 64 * 8; i += 128) csm[i] = 0.f;

    for (int s = 0; s < 1024; s++) {
        const bool enc = (s < 512);
        const int  t   = enc ? s : s - 512;
        const int  e   = enc ? 0 : 1;
        const __half* __restrict__ hin  = g_h16[s & 1];
        __half*       __restrict__ hout = g_h16[(s + 1) & 1];

        // phase start: load this CTA's W_hh slice (enc at s=0, dec at s=512)
        if (s == 0 || s == 512) {
            const __half* src = g_whh[e] + (size_t)c0 * NH_;
            for (int i = tid; i < 32 * 128; i += 128) {
                int r = i >> 7, ch = i & 127;
                cp16(wsm + r * 1032 + ch * 8, src + r * NH_ + ch * 8);
            }
            cp_commit();
            asm volatile("cp.async.wait_group 0;\n");
            __syncthreads();
        }

        // ---- issue all loads: group0 = xw tile + h chunk0; groups 1..7 = h chunks
        {
            const __half* xwsrc = g_xw[e] + (size_t)(t * 64) * NG_ + c0;
            for (int i = tid; i < 256; i += 128) {
                int b = i >> 2, o = (i & 3) * 8;
                cp16(sxw + b * 32 + o, xwsrc + (size_t)b * NG_ + o);
            }
#pragma unroll
            for (int c = 0; c < 8; c++) {
                for (int i = tid; i < 1024; i += 128) {
                    int r = i >> 4, o = (i & 15) * 8;
                    cp16(sA + r * 1032 + c * 128 + o, hin + r * NH_ + c * 128 + o);
                }
                cp_commit();
            }
        }

        float acc[4][4];
#pragma unroll
        for (int i = 0; i < 4; i++)
#pragma unroll
            for (int j = 0; j < 4; j++) acc[i][j] = 0.f;

        // ---- compute chunk c after its group lands (wait_group needs an imm)
#define STEP_CHUNK(C, W)                                                        \
        do {                                                                    \
            asm volatile("cp.async.wait_group %0;\n" :: "n"(W));                \
            __syncthreads();                                                    \
            _Pragma("unroll")                                                   \
            for (int ks = 0; ks < 8; ks++) {                                    \
                uint32_t a[4];                                                  \
                ldsm4(a, sA + (warp * 16 + (lane & 15)) * 1032                  \
                           + (C) * 128 + ks * 16 + ((lane >> 4) << 3));         \
                _Pragma("unroll")                                               \
                for (int n2 = 0; n2 < 2; n2++) {                                \
                    uint32_t b[4];                                              \
                    int nr = n2 * 16 + (lane & 7) + ((lane >> 4) << 3);         \
                    int kc = (C) * 128 + ks * 16 + ((lane >> 3) & 1) * 8;       \
                    ldsm4(b, wsm + nr * 1032 + kc);                             \
                    mma16816(acc[n2 * 2 + 0], a, b[0], b[1]);                   \
                    mma16816(acc[n2 * 2 + 1], a, b[2], b[3]);                   \
                }                                                               \
            }                                                                   \
        } while (0)

        STEP_CHUNK(0, 7);
        STEP_CHUNK(1, 6);
        STEP_CHUNK(2, 5);
        STEP_CHUNK(3, 4);
        STEP_CHUNK(4, 3);
        STEP_CHUNK(5, 2);
        STEP_CHUNK(6, 1);
        STEP_CHUNK(7, 0);
#undef STEP_CHUNK

        // stage accumulators so each lane gathers i,f,g,o of one unit
        {
            int r = lane >> 2;
            float* gw = gsm + warp * (16 * 33);
#pragma unroll
            for (int nt = 0; nt < 4; nt++) {
                int c = nt * 8 + ((lane & 3) << 1);
                gw[r * 33 + c]           = acc[nt][0];
                gw[r * 33 + c + 1]       = acc[nt][1];
                gw[(r + 8) * 33 + c]     = acc[nt][2];
                gw[(r + 8) * 33 + c + 1] = acc[nt][3];
            }
        }
        __syncwarp();

        // LSTM elementwise update: lane handles 4 (b, j) cells
        {
            int rloc = lane >> 1;
            int b    = warp * 16 + rloc;
            int jb   = (lane & 1) * 4;
            const __half* xr = sxw + b * 32;
            const float*  gw = gsm + warp * (16 * 33) + rloc * 33;
            float m = enc ? mask[t * 64 + b] : 1.f;

#pragma unroll
            for (int u = 0; u < 4; u++) {
                int jl  = jb + u;
                int col = jl * 4;
                float gi = gw[col + 0] + __half2float(xr[col + 0]);
                float gf = gw[col + 1] + __half2float(xr[col + 1]);
                float gg = gw[col + 2] + __half2float(xr[col + 2]);
                float go = gw[col + 3] + __half2float(xr[col + 3]);

                float ii = sigmoidf_(gi);
                float ff = sigmoidf_(gf);
                float g2 = tanhf(gg);
                float oo = sigmoidf_(go);

                int   j  = (c0 >> 2) + jl;                 // global hidden unit
                int   ci = b * 8 + jl;                     // c-state index (SMEM)
                float cp = csm[ci];
                float cn = ff * cp + ii * g2;
                float hn = oo * tanhf(cn);

                if (enc) {
                    float hp = __half2float(sA[b * 1032 + j]);  // prev h from SMEM
                    hn = hn * m + hp * (1.f - m);
                    cn = cn * m + cp * (1.f - m);
                }
                csm[ci]            = cn;
                hout[b * NH_ + j]  = __float2half(hn);
                if (!enc) outp[(size_t)(t * 64 + b) * NH_ + j] = hn;
            }
        }

        // ---- grid barrier (release h writes, acquire peers') ----
        if (s != 1023) {
            __threadfence();
            __syncthreads();
            if (tid == 0) {
                unsigned a = atomicAdd(&g_bar_count, 1u);
                if (a == NCTA - 1) {
                    g_bar_count = 0u;
                    __threadfence();
                    atomicAdd(&g_bar_gen, 1u);
                } else {
                    unsigned target = (unsigned)(s + 1);
                    while (*((volatile unsigned*)&g_bar_gen) < target) {
                        __nanosleep(32);
                    }
                }
                __threadfence();
            }
            __syncthreads();
        }
    }
}

// ---------------------------------------------------------------------------
// Launch
// ---------------------------------------------------------------------------
extern "C" void kernel_launch(void* const* d_in, const int* in_sizes, int n_in,
                              void* d_out, int out_size) {
    (void)in_sizes; (void)n_in; (void)out_size;
    const float* input = (const float*)d_in[0];
    const float* mask  = (const float*)d_in[1];
    const float* Wih_e = (const float*)d_in[2];
    const float* Whh_e = (const float*)d_in[3];
    const float* bih_e = (const float*)d_in[4];
    const float* bhh_e = (const float*)d_in[5];
    const float* Wih_d = (const float*)d_in[6];
    const float* Whh_d = (const float*)d_in[7];
    const float* bih_d = (const float*)d_in[8];
    const float* bhh_d = (const float*)d_in[9];
    float* out = (float*)d_out;

    cudaFuncSetAttribute(k_persist, cudaFuncAttributeMaxDynamicSharedMemorySize,
                         SMEM_PERSIST);

    // prep: fp16 conversions, gate-interleaved weight permutation, state reset
    k_convert_x<<<(TB_ * NI_) / 4 / 256, 256>>>(input);
    k_prep<<<2048, 256>>>(Wih_e, Whh_e, bih_e, bhh_e, Wih_d, Whh_d, bih_d, bhh_d);
    k_init<<<(B_ * NH_ + 255) / 256, 256>>>();

    // batched input projections (biases folded in), enc+dec in one launch
    dim3 ggrid(NG_ / 64, TB_ / 64, 2);
    k_xw_gemm<<<ggrid, 128>>>();

    // single persistent kernel: 512 encoder + 512 decoder steps
    k_persist<<<NCTA, 128, SMEM_PERSIST>>>(mask, out);
}